// round 10
// baseline (speedup 1.0000x reference)
#include <cuda_runtime.h>

#define K_DIM 7168
#define E_DIM 256
#define BM 64
#define BN 32
#define BK 16
#define KC_TILES 20   // Eigen kc=320 floats = 20 tiles of BK=16
#define SMEM_BYTES (80 * 1024)   // oversized on purpose: caps occupancy at 2 CTAs/SM

// packed f32x2 FMA (Blackwell): per-component IEEE rn fma
__device__ __forceinline__ unsigned long long ffma2(unsigned long long a,
                                                    unsigned long long b,
                                                    unsigned long long c) {
    unsigned long long d;
    asm("fma.rn.f32x2 %0, %1, %2, %3;" : "=l"(d) : "l"(a), "l"(b), "l"(c));
    return d;
}

__device__ __forceinline__ unsigned long long fadd2(unsigned long long a,
                                                    unsigned long long b) {
    unsigned long long d;
    asm("add.rn.f32x2 %0, %1, %2;" : "=l"(d) : "l"(a), "l"(b));
    return d;
}

__device__ __forceinline__ unsigned long long dup_f32(float a) {
    unsigned long long p;
    asm("mov.b64 %0, {%1, %1};" : "=l"(p) : "r"(__float_as_uint(a)));
    return p;
}

// C[t, e] = sum_k A[t,k] * W[e,k] — fp32, Eigen-blocked accumulation order:
// c = ((0 + S_0) + S_1) + ... ; S_b = ascending-k fma partial over kc=320 block
// (last block = 128). BIT-EXACT match to XLA:CPU Eigen gemm — do not reorder.
// BM=64 x BN=32 tiles, 256 threads, 4m x 2n per thread, accumulators packed
// along m (A pair loads LDS-native; only 2 B dups per k-step -> ALU not binding).
// occ forced to 2 CTAs/SM via 80KB dynamic smem -> 296 slots, 2048 tiles,
// 6.92 tiles/slot -> 98.9% wave utilization.
__global__ __launch_bounds__(256)
void moe_gemm_kernel(const float* __restrict__ A,
                     const float* __restrict__ W,
                     float* __restrict__ C, int T) {
    extern __shared__ char smem_raw[];
    float (*As)[BK][BM] = reinterpret_cast<float (*)[BK][BM]>(smem_raw);
    float (*Bs)[BK][BN] = reinterpret_cast<float (*)[BK][BN]>(smem_raw + 2 * BK * BM * 4);

    const int tid = threadIdx.x;
    const int tx = tid & 15;   // n: 2 experts per thread (16*2=32)
    const int ty = tid >> 4;   // m: 4 tokens per thread  (16*4=64)
    const int n0 = blockIdx.x * BN;   // grid.x = 8 n-tiles (fast: A locality)
    const int m0 = blockIdx.y * BM;   // grid.y = 256 m-tiles

    // A loader: 4 threads per row, one float4 (64 rows x 16 k)
    const int alr = tid >> 2;
    const int alc = (tid & 3) * 4;
    const float* Abase = A + (size_t)(m0 + alr) * K_DIM + alc;
    // B loader: 8 threads per row, one float2 (32 rows x 16 k)
    const int blr = tid >> 3;
    const int blc = (tid & 7) * 2;
    const float* Wbase = W + (size_t)(n0 + blr) * K_DIM + blc;

    // acc[n][mp]: n in {0,1} (expert tx*2+n), mp in {0,1} (m pair: ty*4+2mp,+2mp+1)
    unsigned long long acc[2][2], bac[2][2];
#pragma unroll
    for (int n = 0; n < 2; ++n)
#pragma unroll
        for (int p = 0; p < 2; ++p) { acc[n][p] = 0ull; bac[n][p] = 0ull; }

    float4 aP = *reinterpret_cast<const float4*>(Abase);
    float2 bP = *reinterpret_cast<const float2*>(Wbase);

    const int nIter = K_DIM / BK;  // 448
    for (int kt = 0; kt < nIter; ++kt) {
        const int buf = kt & 1;
        As[buf][alc + 0][alr] = aP.x; As[buf][alc + 1][alr] = aP.y;
        As[buf][alc + 2][alr] = aP.z; As[buf][alc + 3][alr] = aP.w;
        Bs[buf][blc + 0][blr] = bP.x; Bs[buf][blc + 1][blr] = bP.y;
        __syncthreads();

        if (kt + 1 < nIter) {
            aP = *reinterpret_cast<const float4*>(Abase + (size_t)(kt + 1) * BK);
            bP = *reinterpret_cast<const float2*>(Wbase + (size_t)(kt + 1) * BK);
        }

#pragma unroll
        for (int k = 0; k < BK; ++k) {
            // A: 4 consecutive m floats = 2 packed pairs, one LDS.128 (broadcast)
            ulonglong2 ap = *reinterpret_cast<const ulonglong2*>(&As[buf][k][ty * 4]);
            // B: 2 expert floats, each duplicated for packed-m FMA
            float2 bf = *reinterpret_cast<const float2*>(&Bs[buf][k][tx * 2]);
            unsigned long long pb0 = dup_f32(bf.x);
            unsigned long long pb1 = dup_f32(bf.y);
            bac[0][0] = ffma2(ap.x, pb0, bac[0][0]);
            bac[0][1] = ffma2(ap.y, pb0, bac[0][1]);
            bac[1][0] = ffma2(ap.x, pb1, bac[1][0]);
            bac[1][1] = ffma2(ap.y, pb1, bac[1][1]);
        }

        // Eigen kc=320 block boundary: c += S_b; S_b = 0
        if (((kt + 1) % KC_TILES) == 0) {
#pragma unroll
            for (int n = 0; n < 2; ++n)
#pragma unroll
                for (int p = 0; p < 2; ++p) {
                    acc[n][p] = fadd2(acc[n][p], bac[n][p]);
                    bac[n][p] = 0ull;
                }
        }
    }

    // final (remainder 128-wide) block flush
#pragma unroll
    for (int n = 0; n < 2; ++n)
#pragma unroll
        for (int p = 0; p < 2; ++p)
            acc[n][p] = fadd2(acc[n][p], bac[n][p]);

    // epilogue: acc[n][p] component c holds C[m0+ty*4+p*2+c][n0+tx*2+n]
#pragma unroll
    for (int p = 0; p < 2; ++p) {
        float2 a0 = *reinterpret_cast<float2*>(&acc[0][p]);  // n=0, m pair
        float2 a1 = *reinterpret_cast<float2*>(&acc[1][p]);  // n=1, m pair
        int mb = m0 + ty * 4 + p * 2;
        float* c0 = C + (size_t)mb * E_DIM + n0 + tx * 2;
        float* c1 = C + (size_t)(mb + 1) * E_DIM + n0 + tx * 2;
        *reinterpret_cast<float2*>(c0) = make_float2(a0.x, a1.x);
        *reinterpret_cast<float2*>(c1) = make_float2(a0.y, a1.y);
    }
}

// XLA EmitFastTanh replica — UNFUSED mul/add Horner (CPU LLVM does not
// contract), IEEE fdiv, clamp +-7.90531110763549805, |x|<0.0004 -> x.
__device__ __forceinline__ float xla_tanhf_nofma(float x) {
    float xc = fminf(fmaxf(x, -7.90531110763549805f), 7.90531110763549805f);
    float x2 = __fmul_rn(xc, xc);
    float np = -2.76076847742355e-16f;
    np = __fadd_rn(__fmul_rn(x2, np),  2.00018790482477e-13f);
    np = __fadd_rn(__fmul_rn(x2, np), -8.60467152213735e-11f);
    np = __fadd_rn(__fmul_rn(x2, np),  5.12229709037114e-08f);
    np = __fadd_rn(__fmul_rn(x2, np),  1.48572235717979e-05f);
    np = __fadd_rn(__fmul_rn(x2, np),  6.37261928875436e-04f);
    np = __fadd_rn(__fmul_rn(x2, np),  4.89352455891786e-03f);
    float num = __fmul_rn(xc, np);
    float dp = 1.19825839466702e-06f;
    dp = __fadd_rn(__fmul_rn(x2, dp), 1.18534705686654e-04f);
    dp = __fadd_rn(__fmul_rn(x2, dp), 2.26843463243900e-03f);
    dp = __fadd_rn(__fmul_rn(x2, dp), 4.89352518554385e-03f);
    float r = __fdiv_rn(num, dp);
    return (fabsf(x) < 0.0004f) ? x : r;
}

// XLA logistic: 0.5 + 0.5 * tanh(0.5 * x), unfused.
__device__ __forceinline__ float sigmoid_xla(float x) {
    float t = xla_tanhf_nofma(__fmul_rn(0.5f, x));
    return __fadd_rn(0.5f, __fmul_rn(0.5f, t));
}

// one warp per token
__global__ void moe_router_kernel(const float* __restrict__ logits,
                                  float* __restrict__ outW,
                                  float* __restrict__ outI, int T) {
    const unsigned FULL = 0xFFFFFFFFu;
    int warp = (blockIdx.x * blockDim.x + threadIdx.x) >> 5;
    int lane = threadIdx.x & 31;
    if (warp >= T) return;

    const float* row = logits + (size_t)warp * E_DIM;
    float4 v0 = *reinterpret_cast<const float4*>(row + lane * 8);
    float4 v1 = *reinterpret_cast<const float4*>(row + lane * 8 + 4);

    float s[8];
    s[0] = sigmoid_xla(v0.x); s[1] = sigmoid_xla(v0.y);
    s[2] = sigmoid_xla(v0.z); s[3] = sigmoid_xla(v0.w);
    s[4] = sigmoid_xla(v1.x); s[5] = sigmoid_xla(v1.y);
    s[6] = sigmoid_xla(v1.z); s[7] = sigmoid_xla(v1.w);

    // group sum over 32 experts (butterfly tree)
    float f[8];
#pragma unroll
    for (int j = 0; j < 8; ++j)
        f[j] = s[j] + __shfl_xor_sync(FULL, s[j], 2);
    float g[8];
#pragma unroll
    for (int j = 0; j < 8; ++j)
        g[j] = f[j] + __shfl_xor_sync(FULL, f[j], 1);
    float h0 = g[0] + g[4];
    float h1 = g[1] + g[5];
    float h2 = g[2] + g[6];
    float h3 = g[3] + g[7];
    float p0 = h0 + h2;
    float p1 = h1 + h3;
    float mygs = p0 + p1;     // group sum for group (lane>>2)
    int myg = lane >> 2;

    // rank of my group among 8 groups (ties -> lower index, jax top_k)
    int rank = 0;
#pragma unroll
    for (int h = 0; h < 8; ++h) {
        float gh = __shfl_sync(FULL, mygs, h * 4);
        if (h != myg && (gh > mygs || (gh == mygs && h < myg))) rank++;
    }
    bool sel = (rank < 4);

    float ms[8];
#pragma unroll
    for (int j = 0; j < 8; ++j) ms[j] = sel ? s[j] : 0.0f;

    float topv[8];
    int topi[8];
#pragma unroll
    for (int it = 0; it < 8; ++it) {
        float bv = -1.0f;
        int bi = 0;
#pragma unroll
        for (int j = 0; j < 8; ++j) {
            if (ms[j] > bv) { bv = ms[j]; bi = lane * 8 + j; }
        }
#pragma unroll
        for (int off = 16; off; off >>= 1) {
            float ov = __shfl_xor_sync(FULL, bv, off);
            int oi = __shfl_xor_sync(FULL, bi, off);
            if (ov > bv || (ov == bv && oi < bi)) { bv = ov; bi = oi; }
        }
        topv[it] = bv;
        topi[it] = bi;
        if ((bi >> 3) == lane) ms[bi & 7] = -1.0f;
    }

    float denom = 0.f;
#pragma unroll
    for (int it = 0; it < 8; ++it) denom += topv[it];
    denom = fmaxf(denom, 1e-12f);

    if (lane < 8) {
        outW[(size_t)warp * 8 + lane] = __fdiv_rn(topv[lane], denom);
        outI[(size_t)warp * 8 + lane] = (float)topi[lane];
    }
}

extern "C" void kernel_launch(void* const* d_in, const int* in_sizes, int n_in,
                              void* d_out, int out_size) {
    const float* H = (const float*)d_in[0];   // [T, 7168] fp32
    const float* W = (const float*)d_in[1];   // [256, 7168] fp32
    float* out = (float*)d_out;

    int T = in_sizes[0] / K_DIM;

    // output layout: [T*8 weights][T*8 indices][T*256 logits]
    float* outW = out;
    float* outI = out + (size_t)T * 8;
    float* logits = out + (size_t)T * 16;

    cudaFuncSetAttribute(moe_gemm_kernel,
                         cudaFuncAttributeMaxDynamicSharedMemorySize, SMEM_BYTES);

    // grid.x = n-tiles (8) fastest: concurrent window spans ~37 m-tiles (66MB)
    // -> A re-reads stay in L2 (R9 lesson)
    dim3 grid(E_DIM / BN, T / BM);
    moe_gemm_kernel<<<grid, 256, SMEM_BYTES>>>(H, W, logits, T);

    int warps = T;
    int threads = 256;
    int blocks = (warps * 32 + threads - 1) / threads;
    moe_router_kernel<<<blocks, threads>>>(logits, outW, outI, T);
}